// round 7
// baseline (speedup 1.0000x reference)
#include <cuda_runtime.h>
#include <math.h>

// Problem shape (fixed): x [8, 128, 512, 512] f32, conv_w [16,1,3,3], conv_b [16]
// out [8, 1, 512, 512] f32 with per-tile reassembly layout:
//   out_flat = b*HW + seg*16384 + r*128 + c, seg = ti*4 + tj
#define Bb   8
#define Cc   128
#define Hh   512
#define Ww   512
#define HW   (Hh * Ww)        /* 262144 */
#define CHW  (Cc * HW)
#define TS   128              /* tile side */
#define NSEG 16
#define SROWS 32              /* output rows per block */
#define LROWS 34              /* loaded rows incl. 2 halo */

// Per-row channel-L2 accumulation: one warp covers one 128-col row,
// lane l owns float4 group l (512B contiguous per warp per channel).
__device__ __forceinline__ float4 l2_row(const float* __restrict__ xbase,
                                         int gr, int l) {
    float ax = 0.f, ay = 0.f, az = 0.f, aw = 0.f;
    if ((unsigned)gr < (unsigned)TS) {
        const float4* xp = reinterpret_cast<const float4*>(
            xbase + (size_t)gr * Ww) + l;
        #pragma unroll 8
        for (int c = 0; c < Cc; ++c) {
            float4 v = __ldg(xp + (size_t)c * (HW / 4));
            ax = fmaf(v.x, v.x, ax);
            ay = fmaf(v.y, v.y, ay);
            az = fmaf(v.z, v.z, az);
            aw = fmaf(v.w, v.w, aw);
        }
    }
    return make_float4(sqrtf(ax), sqrtf(ay), sqrtf(az), sqrtf(aw));
}

// Fully fused: one block = 32-row x 128-col strip of one (batch, segment) tile.
// Phase 1: l2 map for 34 rows (32 + 2 halo) into SMEM.
// Phase 2: per-tile 3x3 conv (zero pad at tile edges) + bias + sigmoid.
// 512 threads, <=32 regs, 4 blocks/SM -> 100% occupancy, grid 512 = 1 wave.
__global__ void __launch_bounds__(512, 4) fused_kernel(const float* __restrict__ x,
                                                       const float* __restrict__ conv_w,
                                                       const float* __restrict__ conv_b,
                                                       float* __restrict__ out) {
    __shared__ float s[LROWS][128];

    int bid   = blockIdx.x;
    int strip = bid & 3;          // 4 strips of 32 rows per tile
    int seg   = (bid >> 2) & 15;
    int b     = bid >> 6;
    int ti    = seg >> 2;
    int tj    = seg & 3;
    int r0    = strip * SROWS;
    int tid   = threadIdx.x;
    int w     = tid >> 5;         // warp 0..15
    int l     = tid & 31;         // lane = float4 column group

    const float* xbase = x + (size_t)b * CHW + (size_t)(ti * TS) * Ww + tj * TS;

    // ---- Phase 1: rows w, w+16 for all warps; rows 32,33 for warps 0,1 ----
    {
        float4 r = l2_row(xbase, r0 - 1 + w, l);
        *reinterpret_cast<float4*>(&s[w][l * 4]) = r;
    }
    {
        float4 r = l2_row(xbase, r0 - 1 + w + 16, l);
        *reinterpret_cast<float4*>(&s[w + 16][l * 4]) = r;
    }
    if (w < 2) {
        float4 r = l2_row(xbase, r0 - 1 + w + 32, l);
        *reinterpret_cast<float4*>(&s[w + 32][l * 4]) = r;
    }

    // Weights + bias into registers (uniform per block)
    float wt[9];
    const float* wseg = conv_w + seg * 9;
    #pragma unroll
    for (int k = 0; k < 9; ++k) wt[k] = __ldg(wseg + k);
    float bias = __ldg(conv_b + seg);

    __syncthreads();

    // ---- Phase 2: conv + sigmoid. 32 rows x 32 float4 groups = 1024, 2/thread ----
    #pragma unroll
    for (int k = 0; k < 2; ++k) {
        int g    = tid + k * 512;
        int orow = g >> 5;            // output row within strip; smem rows orow..orow+2
        int cq   = (g & 31) * 4;      // output col of first element

        float a0 = 0.f, a1 = 0.f, a2 = 0.f, a3 = 0.f;
        #pragma unroll
        for (int dr = 0; dr < 3; ++dr) {
            const float* sr = s[orow + dr];
            float4 vc = *reinterpret_cast<const float4*>(&sr[cq]);
            float vm1 = (cq == 0)   ? 0.f : sr[cq - 1];
            float vp4 = (cq == 124) ? 0.f : sr[cq + 4];
            float w0 = wt[dr * 3], w1 = wt[dr * 3 + 1], w2 = wt[dr * 3 + 2];
            a0 = fmaf(w0, vm1,  fmaf(w1, vc.x, fmaf(w2, vc.y, a0)));
            a1 = fmaf(w0, vc.x, fmaf(w1, vc.y, fmaf(w2, vc.z, a1)));
            a2 = fmaf(w0, vc.y, fmaf(w1, vc.z, fmaf(w2, vc.w, a2)));
            a3 = fmaf(w0, vc.z, fmaf(w1, vc.w, fmaf(w2, vp4,  a3)));
        }

        float4 o;
        o.x = 1.f / (1.f + __expf(-(a0 + bias)));
        o.y = 1.f / (1.f + __expf(-(a1 + bias)));
        o.z = 1.f / (1.f + __expf(-(a2 + bias)));
        o.w = 1.f / (1.f + __expf(-(a3 + bias)));

        size_t oofs = (size_t)b * HW + (size_t)seg * (TS * TS)
                    + (size_t)(r0 + orow) * TS + cq;
        *reinterpret_cast<float4*>(out + oofs) = o;
    }
}

extern "C" void kernel_launch(void* const* d_in, const int* in_sizes, int n_in,
                              void* d_out, int out_size) {
    const float* x  = (const float*)d_in[0];
    const float* cw = (const float*)d_in[1];
    const float* cb = (const float*)d_in[2];
    float* out = (float*)d_out;

    // 4 strips x 16 segs x 8 batches = 512 blocks, 512 threads each
    fused_kernel<<<Bb * NSEG * 4, 512>>>(x, cw, cb, out);
}

// round 8
// speedup vs baseline: 1.1258x; 1.1258x over previous
#include <cuda_runtime.h>
#include <math.h>

// Problem shape (fixed): x [8, 128, 512, 512] f32, conv_w [16,1,3,3], conv_b [16]
// out [8, 1, 512, 512] f32 with per-tile reassembly layout:
//   out_flat = b*HW + seg*16384 + r*128 + c, seg = ti*4 + tj
#define Bb   8
#define Cc   128
#define Hh   512
#define Ww   512
#define HW   (Hh * Ww)        /* 262144 */
#define CHW  (Cc * HW)
#define TS   128              /* tile side */
#define NSEG 16
#define SROWS 8               /* output rows per block */
#define LROWS 10              /* loaded rows incl. 2 halo */

// Fully fused: one block = 8-row x 128-col strip of one (batch, segment) tile.
// Phase 1: l2 = sqrt(sum_c x^2) for 10 rows (8 + 2 halo) into SMEM.
//          10 warps, one warp per row, lane = float4 column group ->
//          512B contiguous per warp per channel, perfectly balanced.
// Phase 2: per-tile 3x3 conv (zero pad at tile edges) + bias + sigmoid,
//          threads 0..255: one float4 output group each.
// 320 threads, <=32 regs -> 6 blocks/SM (1920 thr, 94% occ), 2048 blocks.
__global__ void __launch_bounds__(320, 6) fused_kernel(const float* __restrict__ x,
                                                       const float* __restrict__ conv_w,
                                                       const float* __restrict__ conv_b,
                                                       float* __restrict__ out) {
    __shared__ float s[LROWS][128];

    int bid   = blockIdx.x;
    int strip = bid & 15;         // 16 strips of 8 rows per tile
    int seg   = (bid >> 4) & 15;
    int b     = bid >> 8;
    int ti    = seg >> 2;
    int tj    = seg & 3;
    int r0    = strip * SROWS;
    int tid   = threadIdx.x;
    int w     = tid >> 5;         // warp 0..9 = smem row
    int l     = tid & 31;         // lane = float4 column group

    // ---- Phase 1: channel-L2, one row per warp ----
    {
        int gr = r0 - 1 + w;      // row within tile (-1 .. 128)
        float ax = 0.f, ay = 0.f, az = 0.f, aw = 0.f;
        if ((unsigned)gr < (unsigned)TS) {
            const float4* xp = reinterpret_cast<const float4*>(
                x + (size_t)b * CHW + (size_t)(ti * TS + gr) * Ww + tj * TS) + l;
            #pragma unroll 8
            for (int c = 0; c < Cc; ++c) {
                float4 v = __ldg(xp + (size_t)c * (HW / 4));
                ax = fmaf(v.x, v.x, ax);
                ay = fmaf(v.y, v.y, ay);
                az = fmaf(v.z, v.z, az);
                aw = fmaf(v.w, v.w, aw);
            }
        }
        float4 r;
        r.x = sqrtf(ax); r.y = sqrtf(ay); r.z = sqrtf(az); r.w = sqrtf(aw);
        *reinterpret_cast<float4*>(&s[w][l * 4]) = r;
    }

    // Weights + bias into registers (uniform per block)
    float wt[9];
    const float* wseg = conv_w + seg * 9;
    #pragma unroll
    for (int k = 0; k < 9; ++k) wt[k] = __ldg(wseg + k);
    float bias = __ldg(conv_b + seg);

    __syncthreads();

    // ---- Phase 2: conv + sigmoid. 8 rows x 32 float4 groups = 256 threads ----
    if (tid < 256) {
        int orow = tid >> 5;          // output row within strip; smem rows orow..orow+2
        int cq   = (tid & 31) * 4;    // output col of first element

        float a0 = 0.f, a1 = 0.f, a2 = 0.f, a3 = 0.f;
        #pragma unroll
        for (int dr = 0; dr < 3; ++dr) {
            const float* sr = s[orow + dr];
            float4 vc = *reinterpret_cast<const float4*>(&sr[cq]);
            float vm1 = (cq == 0)   ? 0.f : sr[cq - 1];
            float vp4 = (cq == 124) ? 0.f : sr[cq + 4];
            float w0 = wt[dr * 3], w1 = wt[dr * 3 + 1], w2 = wt[dr * 3 + 2];
            a0 = fmaf(w0, vm1,  fmaf(w1, vc.x, fmaf(w2, vc.y, a0)));
            a1 = fmaf(w0, vc.x, fmaf(w1, vc.y, fmaf(w2, vc.z, a1)));
            a2 = fmaf(w0, vc.y, fmaf(w1, vc.z, fmaf(w2, vc.w, a2)));
            a3 = fmaf(w0, vc.z, fmaf(w1, vc.w, fmaf(w2, vp4,  a3)));
        }

        float4 o;
        o.x = 1.f / (1.f + __expf(-(a0 + bias)));
        o.y = 1.f / (1.f + __expf(-(a1 + bias)));
        o.z = 1.f / (1.f + __expf(-(a2 + bias)));
        o.w = 1.f / (1.f + __expf(-(a3 + bias)));

        size_t oofs = (size_t)b * HW + (size_t)seg * (TS * TS)
                    + (size_t)(r0 + orow) * TS + cq;
        *reinterpret_cast<float4*>(out + oofs) = o;
    }
}

extern "C" void kernel_launch(void* const* d_in, const int* in_sizes, int n_in,
                              void* d_out, int out_size) {
    const float* x  = (const float*)d_in[0];
    const float* cw = (const float*)d_in[1];
    const float* cb = (const float*)d_in[2];
    float* out = (float*)d_out;

    // 16 strips x 16 segs x 8 batches = 2048 blocks, 320 threads each
    fused_kernel<<<Bb * NSEG * 16, 320>>>(x, cw, cb, out);
}